// round 1
// baseline (speedup 1.0000x reference)
#include <cuda_runtime.h>

#define N_MAX 100000
#define E_MAX 1600000
#define D 256

// ---- scratch (static device globals; no allocation) ----
__device__ int   g_out_deg[N_MAX];
__device__ int   g_in_deg[N_MAX];
__device__ float g_pre[N_MAX];
__device__ int   g_row_ptr[N_MAX + 1];
__device__ int   g_fill[N_MAX];
__device__ int   g_csr_src[E_MAX];
__device__ int   g_blksum[128];
__device__ int   g_blkoff[128];
__device__ float g_agg[(size_t)N_MAX * D];

// ---- zero degree/fill counters ----
__global__ void k_zero(int n) {
    int i = blockIdx.x * blockDim.x + threadIdx.x;
    if (i < n) { g_out_deg[i] = 0; g_in_deg[i] = 0; g_fill[i] = 0; }
}

// ---- degree histograms ----
__global__ void k_deg(const int* __restrict__ src, const int* __restrict__ dst, int e) {
    int i = blockIdx.x * blockDim.x + threadIdx.x;
    if (i < e) {
        atomicAdd(&g_out_deg[src[i]], 1);
        atomicAdd(&g_in_deg[dst[i]], 1);
    }
}

// ---- pre-scale = out_deg^-0.5 (clipped at 1) ----
__global__ void k_pre(int n) {
    int i = blockIdx.x * blockDim.x + threadIdx.x;
    if (i < n) g_pre[i] = rsqrtf((float)max(g_out_deg[i], 1));
}

// ---- 3-phase scan of in_deg -> row_ptr (exclusive) ----
__global__ void k_scan_local(int n) {
    __shared__ int s[1024];
    int i = blockIdx.x * 1024 + threadIdx.x;
    int v = (i < n) ? g_in_deg[i] : 0;
    s[threadIdx.x] = v;
    __syncthreads();
    for (int off = 1; off < 1024; off <<= 1) {
        int t = (threadIdx.x >= off) ? s[threadIdx.x - off] : 0;
        __syncthreads();
        s[threadIdx.x] += t;
        __syncthreads();
    }
    if (i < n) g_row_ptr[i + 1] = s[threadIdx.x];
    if (threadIdx.x == 1023) g_blksum[blockIdx.x] = s[1023];
}

__global__ void k_scan_blk(int nb) {
    __shared__ int s[128];
    int t = threadIdx.x;
    int v = (t < nb) ? g_blksum[t] : 0;
    s[t] = v;
    __syncthreads();
    for (int off = 1; off < 128; off <<= 1) {
        int u = (t >= off) ? s[t - off] : 0;
        __syncthreads();
        s[t] += u;
        __syncthreads();
    }
    g_blkoff[t] = s[t] - v;  // exclusive prefix of block sums
}

__global__ void k_scan_add(int n) {
    int i = blockIdx.x * blockDim.x + threadIdx.x;
    if (i < n) g_row_ptr[i + 1] += g_blkoff[i >> 10];
    if (i == 0) g_row_ptr[0] = 0;
}

// ---- counting-sort edges by dst into CSR ----
__global__ void k_fill(const int* __restrict__ src, const int* __restrict__ dst, int e) {
    int i = blockIdx.x * blockDim.x + threadIdx.x;
    if (i < e) {
        int d  = dst[i];
        int pos = g_row_ptr[d] + atomicAdd(&g_fill[d], 1);
        g_csr_src[pos] = src[i];
    }
}

// ---- aggregation: one 64-thread group per node, float4 lanes, 2-edge unroll ----
__global__ __launch_bounds__(256) void k_agg(const float4* __restrict__ feat4, int n) {
    int node = blockIdx.x * 4 + (threadIdx.x >> 6);
    int lane = threadIdx.x & 63;
    if (node >= n) return;
    int beg = g_row_ptr[node];
    int end = g_row_ptr[node + 1];
    float4 acc = make_float4(0.f, 0.f, 0.f, 0.f);
    int j = beg;
    for (; j + 2 <= end; j += 2) {
        int   s0 = g_csr_src[j];
        int   s1 = g_csr_src[j + 1];
        float p0 = g_pre[s0];
        float p1 = g_pre[s1];
        float4 v0 = feat4[(size_t)s0 * 64 + lane];
        float4 v1 = feat4[(size_t)s1 * 64 + lane];
        acc.x += p0 * v0.x + p1 * v1.x;
        acc.y += p0 * v0.y + p1 * v1.y;
        acc.z += p0 * v0.z + p1 * v1.z;
        acc.w += p0 * v0.w + p1 * v1.w;
    }
    if (j < end) {
        int   s0 = g_csr_src[j];
        float p0 = g_pre[s0];
        float4 v0 = feat4[(size_t)s0 * 64 + lane];
        acc.x += p0 * v0.x;
        acc.y += p0 * v0.y;
        acc.z += p0 * v0.z;
        acc.w += p0 * v0.w;
    }
    *(float4*)&g_agg[(size_t)node * D + lane * 4] = acc;
}

// ---- GEMM: C = agg @ W, fused post-scale + bias. 128x128x8, 8x8/thread ----
__global__ __launch_bounds__(256) void k_gemm(const float* __restrict__ W,
                                              const float* __restrict__ bias,
                                              float* __restrict__ C, int n) {
    __shared__ float sA[8][128];
    __shared__ float sW[8][128];
    const int tid = threadIdx.x;
    const int tx = tid & 15;
    const int ty = tid >> 4;
    const int row0 = blockIdx.y * 128;
    const int col0 = blockIdx.x * 128;

    float acc[8][8];
#pragma unroll
    for (int i = 0; i < 8; i++)
#pragma unroll
        for (int j = 0; j < 8; j++) acc[i][j] = 0.f;

    const int ar = tid >> 1;        // 0..127
    const int ac = (tid & 1) * 4;   // 0 or 4
    const int wr = tid >> 5;        // 0..7
    const int wc = (tid & 31) * 4;  // 0..124

    for (int k0 = 0; k0 < D; k0 += 8) {
        int gr = row0 + ar;
        float4 av = make_float4(0.f, 0.f, 0.f, 0.f);
        if (gr < n) av = *(const float4*)&g_agg[(size_t)gr * D + k0 + ac];
        sA[ac + 0][ar] = av.x;
        sA[ac + 1][ar] = av.y;
        sA[ac + 2][ar] = av.z;
        sA[ac + 3][ar] = av.w;
        float4 wv = *(const float4*)&W[(size_t)(k0 + wr) * D + col0 + wc];
        *(float4*)&sW[wr][wc] = wv;
        __syncthreads();
#pragma unroll
        for (int kk = 0; kk < 8; kk++) {
            float a[8], w[8];
            *(float4*)&a[0] = *(const float4*)&sA[kk][ty * 8];
            *(float4*)&a[4] = *(const float4*)&sA[kk][ty * 8 + 4];
            *(float4*)&w[0] = *(const float4*)&sW[kk][tx * 8];
            *(float4*)&w[4] = *(const float4*)&sW[kk][tx * 8 + 4];
#pragma unroll
            for (int i = 0; i < 8; i++)
#pragma unroll
                for (int j = 0; j < 8; j++)
                    acc[i][j] = fmaf(a[i], w[j], acc[i][j]);
        }
        __syncthreads();
    }

#pragma unroll
    for (int i = 0; i < 8; i++) {
        int row = row0 + ty * 8 + i;
        if (row < n) {
            float post = rsqrtf(fmaxf((float)g_in_deg[row], 1.f));
#pragma unroll
            for (int j = 0; j < 8; j += 4) {
                int col = col0 + tx * 8 + j;
                float4 o;
                o.x = acc[i][j + 0] * post + bias[col + 0];
                o.y = acc[i][j + 1] * post + bias[col + 1];
                o.z = acc[i][j + 2] * post + bias[col + 2];
                o.w = acc[i][j + 3] * post + bias[col + 3];
                *(float4*)&C[(size_t)row * D + col] = o;
            }
        }
    }
}

extern "C" void kernel_launch(void* const* d_in, const int* in_sizes, int n_in,
                              void* d_out, int out_size) {
    const float* feat   = (const float*)d_in[0];
    const int*   src    = (const int*)d_in[1];
    const int*   dst    = (const int*)d_in[2];
    const float* weight = (const float*)d_in[3];
    const float* bias   = (const float*)d_in[4];
    float*       out    = (float*)d_out;

    int n = in_sizes[0] / D;   // 100000
    int e = in_sizes[1];       // 1600000

    k_zero<<<(n + 255) / 256, 256>>>(n);
    k_deg<<<(e + 255) / 256, 256>>>(src, dst, e);
    k_pre<<<(n + 255) / 256, 256>>>(n);

    int nb = (n + 1023) / 1024;  // 98
    k_scan_local<<<nb, 1024>>>(n);
    k_scan_blk<<<1, 128>>>(nb);
    k_scan_add<<<(n + 255) / 256, 256>>>(n);

    k_fill<<<(e + 255) / 256, 256>>>(src, dst, e);

    k_agg<<<(n + 3) / 4, 256>>>((const float4*)feat, n);

    dim3 gg(D / 128, (n + 127) / 128);
    k_gemm<<<gg, 256>>>(weight, bias, out, n);
}

// round 3
// speedup vs baseline: 1.7124x; 1.7124x over previous
#include <cuda_runtime.h>
#include <cstdint>

#define N_MAX 100000
#define E_MAX 1600000
#define D 256

// ---- scratch (static device globals; no allocation) ----
__device__ int      g_out_deg[N_MAX];
__device__ int      g_in_deg[N_MAX];
__device__ float    g_pre[N_MAX];
__device__ int      g_row_ptr[N_MAX + 1];
__device__ int      g_fill[N_MAX];
__device__ int      g_csr_src[E_MAX];
__device__ int      g_blksum[128];
__device__ int      g_blkoff[128];
__device__ float    g_agg[(size_t)N_MAX * D];
__device__ uint32_t g_wt32[D * D];   // W as tf32-rounded bits, row-major [k][n]

// ======================= setup kernels =======================
__global__ void k_zero(int n) {
    int i = blockIdx.x * blockDim.x + threadIdx.x;
    if (i < n) { g_out_deg[i] = 0; g_in_deg[i] = 0; g_fill[i] = 0; }
}

__global__ void k_deg(const int* __restrict__ src, const int* __restrict__ dst, int e) {
    int i = blockIdx.x * blockDim.x + threadIdx.x;
    if (i < e) {
        atomicAdd(&g_out_deg[src[i]], 1);
        atomicAdd(&g_in_deg[dst[i]], 1);
    }
}

__global__ void k_pre(int n) {
    int i = blockIdx.x * blockDim.x + threadIdx.x;
    if (i < n) g_pre[i] = rsqrtf((float)max(g_out_deg[i], 1));
}

// convert W to tf32-rounded bit patterns (once per call; 65536 elems)
__global__ void k_wcvt(const float* __restrict__ W) {
    int i = blockIdx.x * blockDim.x + threadIdx.x;
    if (i < D * D) {
        uint32_t u;
        asm("cvt.rna.tf32.f32 %0, %1;" : "=r"(u) : "f"(W[i]));
        g_wt32[i] = u;
    }
}

__global__ void k_scan_local(int n) {
    __shared__ int s[1024];
    int i = blockIdx.x * 1024 + threadIdx.x;
    int v = (i < n) ? g_in_deg[i] : 0;
    s[threadIdx.x] = v;
    __syncthreads();
    for (int off = 1; off < 1024; off <<= 1) {
        int t = (threadIdx.x >= off) ? s[threadIdx.x - off] : 0;
        __syncthreads();
        s[threadIdx.x] += t;
        __syncthreads();
    }
    if (i < n) g_row_ptr[i + 1] = s[threadIdx.x];
    if (threadIdx.x == 1023) g_blksum[blockIdx.x] = s[1023];
}

__global__ void k_scan_blk(int nb) {
    __shared__ int s[128];
    int t = threadIdx.x;
    int v = (t < nb) ? g_blksum[t] : 0;
    s[t] = v;
    __syncthreads();
    for (int off = 1; off < 128; off <<= 1) {
        int u = (t >= off) ? s[t - off] : 0;
        __syncthreads();
        s[t] += u;
        __syncthreads();
    }
    g_blkoff[t] = s[t] - v;
}

__global__ void k_scan_add(int n) {
    int i = blockIdx.x * blockDim.x + threadIdx.x;
    if (i < n) g_row_ptr[i + 1] += g_blkoff[i >> 10];
    if (i == 0) g_row_ptr[0] = 0;
}

__global__ void k_fill(const int* __restrict__ src, const int* __restrict__ dst, int e) {
    int i = blockIdx.x * blockDim.x + threadIdx.x;
    if (i < e) {
        int d = dst[i];
        int pos = g_row_ptr[d] + atomicAdd(&g_fill[d], 1);
        g_csr_src[pos] = src[i];
    }
}

// ======================= aggregation =======================
__global__ __launch_bounds__(256) void k_agg(const float4* __restrict__ feat4, int n) {
    int node = blockIdx.x * 4 + (threadIdx.x >> 6);
    int lane = threadIdx.x & 63;
    if (node >= n) return;
    int beg = g_row_ptr[node];
    int end = g_row_ptr[node + 1];
    float4 acc = make_float4(0.f, 0.f, 0.f, 0.f);
    int j = beg;
    for (; j + 2 <= end; j += 2) {
        int   s0 = g_csr_src[j];
        int   s1 = g_csr_src[j + 1];
        float p0 = g_pre[s0];
        float p1 = g_pre[s1];
        float4 v0 = feat4[(size_t)s0 * 64 + lane];
        float4 v1 = feat4[(size_t)s1 * 64 + lane];
        acc.x += p0 * v0.x + p1 * v1.x;
        acc.y += p0 * v0.y + p1 * v1.y;
        acc.z += p0 * v0.z + p1 * v1.z;
        acc.w += p0 * v0.w + p1 * v1.w;
    }
    if (j < end) {
        int   s0 = g_csr_src[j];
        float p0 = g_pre[s0];
        float4 v0 = feat4[(size_t)s0 * 64 + lane];
        acc.x += p0 * v0.x;
        acc.y += p0 * v0.y;
        acc.z += p0 * v0.z;
        acc.w += p0 * v0.w;
    }
    *(float4*)&g_agg[(size_t)node * D + lane * 4] = acc;
}

// ======================= tf32 warp-MMA GEMM =======================
// C[n, 256] = agg[n, 256] @ W[256, 256], fused post-scale + bias.
// CTA tile 128x128, 8 warps (2 m x 4 n), warp tile 64x32 = 4x4 m16n8k8 frags.
// sA: [m][k] stride 36 (uint32 tf32 bits), sB: [k][n] stride 136.

#define SA_STRIDE 36
#define SB_STRIDE 136

__device__ __forceinline__ void mma_tf32(float* c, const uint32_t* a, const uint32_t* b) {
    asm volatile(
        "mma.sync.aligned.m16n8k8.row.col.f32.tf32.tf32.f32 "
        "{%0,%1,%2,%3}, {%4,%5,%6,%7}, {%8,%9}, {%0,%1,%2,%3};"
        : "+f"(c[0]), "+f"(c[1]), "+f"(c[2]), "+f"(c[3])
        : "r"(a[0]), "r"(a[1]), "r"(a[2]), "r"(a[3]), "r"(b[0]), "r"(b[1]));
}

__device__ __forceinline__ uint32_t f2tf32(float f) {
    uint32_t u;
    asm("cvt.rna.tf32.f32 %0, %1;" : "=r"(u) : "f"(f));
    return u;
}

__global__ __launch_bounds__(256, 2) void k_gemm_mma(const float* __restrict__ bias,
                                                     float* __restrict__ out, int n) {
    __shared__ uint32_t sA[128 * SA_STRIDE];   // [m][k] 128 x 32 (+pad)
    __shared__ uint32_t sB[32 * SB_STRIDE];    // [k][n] 32 x 128 (+pad)

    const int tid = threadIdx.x;
    const int wid = tid >> 5;
    const int lid = tid & 31;
    const int g   = lid >> 2;    // 0..7
    const int t   = lid & 3;     // 0..3
    const int wm  = wid & 1;     // 0..1 (m-warp)
    const int wn  = wid >> 1;    // 0..3 (n-warp)

    const int row0 = blockIdx.y * 128;
    const int n0   = blockIdx.x * 128;
    const int arows = min(128, n - row0);

    float acc[4][4][4];
#pragma unroll
    for (int mf = 0; mf < 4; mf++)
#pragma unroll
        for (int nf = 0; nf < 4; nf++)
#pragma unroll
            for (int r = 0; r < 4; r++) acc[mf][nf][r] = 0.f;

    // per-thread load coords
    const int a_r  = tid >> 1;          // 0..127 row of A (2 threads/row)
    const int a_c4 = (tid & 1) * 4;     // 0 or 4 -> float4 at k-offset a_c4*? (below: 2 float4/row-half)
    // A tile is 128 rows x 32 k: 8 float4 per row; thread tid covers idx=tid+i*256
    // B tile is 32 k-rows x 128 n: 32 uint4 per k-row; idx=tid+i*256

    for (int kc = 0; kc < 8; kc++) {
        const int kbase = kc * 32;
        // ---- load A (coalesced: 4 float4 per thread), cvt to tf32, STS.128 ----
#pragma unroll
        for (int i = 0; i < 4; i++) {
            int idx = tid + i * 256;        // 0..1023
            int r   = idx >> 3;             // 0..127
            int c4  = (idx & 7) * 4;        // 0,4,..28
            float4 v = make_float4(0.f, 0.f, 0.f, 0.f);
            if (r < arows)
                v = *(const float4*)&g_agg[(size_t)(row0 + r) * D + kbase + c4];
            uint4 u;
            u.x = f2tf32(v.x); u.y = f2tf32(v.y); u.z = f2tf32(v.z); u.w = f2tf32(v.w);
            *(uint4*)&sA[r * SA_STRIDE + c4] = u;
        }
        // ---- load B (already tf32 bits), STS.128 ----
#pragma unroll
        for (int i = 0; i < 4; i++) {
            int idx = tid + i * 256;
            int kr  = idx >> 5;             // 0..31
            int c4  = (idx & 31) * 4;       // 0..124
            uint4 u = *(const uint4*)&g_wt32[(size_t)(kbase + kr) * D + n0 + c4];
            *(uint4*)&sB[kr * SB_STRIDE + c4] = u;
        }
        __syncthreads();

        // ---- 4 k8-steps ----
#pragma unroll
        for (int ks = 0; ks < 4; ks++) {
            const int k0 = ks * 8;
            uint32_t af[4][4], bf[4][2];
#pragma unroll
            for (int mf = 0; mf < 4; mf++) {
                int mrow = wm * 64 + mf * 16 + g;
                const uint32_t* base = &sA[mrow * SA_STRIDE + k0 + t];
                af[mf][0] = base[0];
                af[mf][1] = base[8 * SA_STRIDE];
                af[mf][2] = base[4];
                af[mf][3] = base[8 * SA_STRIDE + 4];
            }
#pragma unroll
            for (int nf = 0; nf < 4; nf++) {
                int ncol = wn * 32 + nf * 8 + g;
                bf[nf][0] = sB[(k0 + t) * SB_STRIDE + ncol];
                bf[nf][1] = sB[(k0 + t + 4) * SB_STRIDE + ncol];
            }
#pragma unroll
            for (int mf = 0; mf < 4; mf++)
#pragma unroll
                for (int nf = 0; nf < 4; nf++)
                    mma_tf32(acc[mf][nf], af[mf], bf[nf]);
        }
        __syncthreads();
    }

    // ---- epilogue: post-scale + bias ----
#pragma unroll
    for (int mf = 0; mf < 4; mf++) {
        int r0 = row0 + wm * 64 + mf * 16 + g;
        int r1 = r0 + 8;
        float post0 = 0.f, post1 = 0.f;
        if (r0 < n) post0 = rsqrtf(fmaxf((float)g_in_deg[r0], 1.f));
        if (r1 < n) post1 = rsqrtf(fmaxf((float)g_in_deg[r1], 1.f));
#pragma unroll
        for (int nf = 0; nf < 4; nf++) {
            int c = n0 + wn * 32 + nf * 8 + t * 2;
            float2 b2 = *(const float2*)&bias[c];
            if (r0 < n) {
                float2 v;
                v.x = acc[mf][nf][0] * post0 + b2.x;
                v.y = acc[mf][nf][1] * post0 + b2.y;
                *(float2*)&out[(size_t)r0 * D + c] = v;
            }
            if (r1 < n) {
                float2 v;
                v.x = acc[mf][nf][2] * post1 + b2.x;
                v.y = acc[mf][nf][3] * post1 + b2.y;
                *(float2*)&out[(size_t)r1 * D + c] = v;
            }
        }
    }
}

// ======================= launch =======================
extern "C" void kernel_launch(void* const* d_in, const int* in_sizes, int n_in,
                              void* d_out, int out_size) {
    const float* feat   = (const float*)d_in[0];
    const int*   src    = (const int*)d_in[1];
    const int*   dst    = (const int*)d_in[2];
    const float* weight = (const float*)d_in[3];
    const float* bias   = (const float*)d_in[4];
    float*       out    = (float*)d_out;

    int n = in_sizes[0] / D;   // 100000
    int e = in_sizes[1];       // 1600000

    k_zero<<<(n + 255) / 256, 256>>>(n);
    k_deg<<<(e + 255) / 256, 256>>>(src, dst, e);
    k_pre<<<(n + 255) / 256, 256>>>(n);
    k_wcvt<<<(D * D + 255) / 256, 256>>>(weight);

    int nb = (n + 1023) / 1024;
    k_scan_local<<<nb, 1024>>>(n);
    k_scan_blk<<<1, 128>>>(nb);
    k_scan_add<<<(n + 255) / 256, 256>>>(n);

    k_fill<<<(e + 255) / 256, 256>>>(src, dst, e);

    k_agg<<<(n + 3) / 4, 256>>>((const float4*)feat, n);

    dim3 gg(2, (n + 127) / 128);
    k_gemm_mma<<<gg, 256>>>(bias, out, n);
}

// round 4
// speedup vs baseline: 2.0910x; 1.2211x over previous
#include <cuda_runtime.h>
#include <cuda_fp16.h>
#include <cstdint>

#define N_MAX 100000
#define E_MAX 1600000
#define D 256

// ---- scratch (static device globals; no allocation) ----
__device__ int      g_out_deg[N_MAX];
__device__ int      g_in_deg[N_MAX];
__device__ float    g_pre[N_MAX];
__device__ int      g_row_ptr[N_MAX + 1];
__device__ int      g_fill[N_MAX];
__device__ int      g_csr_src[E_MAX];
__device__ int      g_blksum[128];
__device__ int      g_blkoff[128];
__device__ float    g_agg[(size_t)N_MAX * D];
__device__ __half   g_feat16[(size_t)N_MAX * D];  // pre-scaled fp16 features
__device__ uint32_t g_wt32[D * D];                // W as tf32 bits, row-major [k][n]

// ======================= setup kernels =======================
__global__ void k_zero(int n) {
    int i = blockIdx.x * blockDim.x + threadIdx.x;
    if (i < n) { g_out_deg[i] = 0; g_in_deg[i] = 0; g_fill[i] = 0; }
}

__global__ void k_deg(const int* __restrict__ src, const int* __restrict__ dst, int e) {
    int i = blockIdx.x * blockDim.x + threadIdx.x;
    if (i < e) {
        atomicAdd(&g_out_deg[src[i]], 1);
        atomicAdd(&g_in_deg[dst[i]], 1);
    }
}

__global__ void k_pre(int n) {
    int i = blockIdx.x * blockDim.x + threadIdx.x;
    if (i < n) g_pre[i] = rsqrtf((float)max(g_out_deg[i], 1));
}

// feat -> fp16 with pre-scale fused. One thread per 8 floats (n*32 threads).
__global__ void k_feat16(const float4* __restrict__ feat4, int n) {
    int idx = blockIdx.x * blockDim.x + threadIdx.x;
    if (idx >= n * 32) return;
    int node = idx >> 5;
    float p = g_pre[node];
    float4 v0 = feat4[(size_t)idx * 2];
    float4 v1 = feat4[(size_t)idx * 2 + 1];
    __half2 h[4];
    h[0] = __floats2half2_rn(v0.x * p, v0.y * p);
    h[1] = __floats2half2_rn(v0.z * p, v0.w * p);
    h[2] = __floats2half2_rn(v1.x * p, v1.y * p);
    h[3] = __floats2half2_rn(v1.z * p, v1.w * p);
    *(uint4*)&g_feat16[(size_t)idx * 8] = *(uint4*)h;
}

// convert W to tf32-rounded bit patterns
__global__ void k_wcvt(const float* __restrict__ W) {
    int i = blockIdx.x * blockDim.x + threadIdx.x;
    if (i < D * D) {
        uint32_t u;
        asm("cvt.rna.tf32.f32 %0, %1;" : "=r"(u) : "f"(W[i]));
        g_wt32[i] = u;
    }
}

__global__ void k_scan_local(int n) {
    __shared__ int s[1024];
    int i = blockIdx.x * 1024 + threadIdx.x;
    int v = (i < n) ? g_in_deg[i] : 0;
    s[threadIdx.x] = v;
    __syncthreads();
    for (int off = 1; off < 1024; off <<= 1) {
        int t = (threadIdx.x >= off) ? s[threadIdx.x - off] : 0;
        __syncthreads();
        s[threadIdx.x] += t;
        __syncthreads();
    }
    if (i < n) g_row_ptr[i + 1] = s[threadIdx.x];
    if (threadIdx.x == 1023) g_blksum[blockIdx.x] = s[1023];
}

__global__ void k_scan_blk(int nb) {
    __shared__ int s[128];
    int t = threadIdx.x;
    int v = (t < nb) ? g_blksum[t] : 0;
    s[t] = v;
    __syncthreads();
    for (int off = 1; off < 128; off <<= 1) {
        int u = (t >= off) ? s[t - off] : 0;
        __syncthreads();
        s[t] += u;
        __syncthreads();
    }
    g_blkoff[t] = s[t] - v;
}

__global__ void k_scan_add(int n) {
    int i = blockIdx.x * blockDim.x + threadIdx.x;
    if (i < n) g_row_ptr[i + 1] += g_blkoff[i >> 10];
    if (i == 0) g_row_ptr[0] = 0;
}

__global__ void k_fill(const int* __restrict__ src, const int* __restrict__ dst, int e) {
    int i = blockIdx.x * blockDim.x + threadIdx.x;
    if (i < e) {
        int d = dst[i];
        int pos = g_row_ptr[d] + atomicAdd(&g_fill[d], 1);
        g_csr_src[pos] = src[i];
    }
}

// ======================= aggregation (fp16 gather, fp32 accumulate) =======================
__device__ __forceinline__ void acc8(float* acc, uint4 u) {
    __half2* h = (__half2*)&u;
    float2 a0 = __half22float2(h[0]);
    float2 a1 = __half22float2(h[1]);
    float2 a2 = __half22float2(h[2]);
    float2 a3 = __half22float2(h[3]);
    acc[0] += a0.x; acc[1] += a0.y;
    acc[2] += a1.x; acc[3] += a1.y;
    acc[4] += a2.x; acc[5] += a2.y;
    acc[6] += a3.x; acc[7] += a3.y;
}

__global__ __launch_bounds__(256) void k_agg(int n) {
    int node = blockIdx.x * 8 + (threadIdx.x >> 5);
    int lane = threadIdx.x & 31;
    if (node >= n) return;
    int beg = g_row_ptr[node];
    int end = g_row_ptr[node + 1];
    const uint4* f = (const uint4*)g_feat16;  // 32 uint4 per row
    float acc[8];
#pragma unroll
    for (int i = 0; i < 8; i++) acc[i] = 0.f;
    int j = beg;
    for (; j + 2 <= end; j += 2) {
        int s0 = g_csr_src[j];
        int s1 = g_csr_src[j + 1];
        uint4 u0 = f[(size_t)s0 * 32 + lane];
        uint4 u1 = f[(size_t)s1 * 32 + lane];
        acc8(acc, u0);
        acc8(acc, u1);
    }
    if (j < end) {
        int s0 = g_csr_src[j];
        uint4 u0 = f[(size_t)s0 * 32 + lane];
        acc8(acc, u0);
    }
    float* o = &g_agg[(size_t)node * D + lane * 8];
    *(float4*)(o + 0) = make_float4(acc[0], acc[1], acc[2], acc[3]);
    *(float4*)(o + 4) = make_float4(acc[4], acc[5], acc[6], acc[7]);
}

// ======================= tf32 warp-MMA GEMM =======================
#define SA_STRIDE 36
#define SB_STRIDE 136

__device__ __forceinline__ void mma_tf32(float* c, const uint32_t* a, const uint32_t* b) {
    asm volatile(
        "mma.sync.aligned.m16n8k8.row.col.f32.tf32.tf32.f32 "
        "{%0,%1,%2,%3}, {%4,%5,%6,%7}, {%8,%9}, {%0,%1,%2,%3};"
        : "+f"(c[0]), "+f"(c[1]), "+f"(c[2]), "+f"(c[3])
        : "r"(a[0]), "r"(a[1]), "r"(a[2]), "r"(a[3]), "r"(b[0]), "r"(b[1]));
}

__device__ __forceinline__ uint32_t f2tf32(float f) {
    uint32_t u;
    asm("cvt.rna.tf32.f32 %0, %1;" : "=r"(u) : "f"(f));
    return u;
}

__global__ __launch_bounds__(256, 2) void k_gemm_mma(const float* __restrict__ bias,
                                                     float* __restrict__ out, int n) {
    __shared__ uint32_t sA[128 * SA_STRIDE];
    __shared__ uint32_t sB[32 * SB_STRIDE];

    const int tid = threadIdx.x;
    const int wid = tid >> 5;
    const int lid = tid & 31;
    const int g   = lid >> 2;
    const int t   = lid & 3;
    const int wm  = wid & 1;
    const int wn  = wid >> 1;

    const int row0 = blockIdx.y * 128;
    const int n0   = blockIdx.x * 128;
    const int arows = min(128, n - row0);

    float acc[4][4][4];
#pragma unroll
    for (int mf = 0; mf < 4; mf++)
#pragma unroll
        for (int nf = 0; nf < 4; nf++)
#pragma unroll
            for (int r = 0; r < 4; r++) acc[mf][nf][r] = 0.f;

    for (int kc = 0; kc < 8; kc++) {
        const int kbase = kc * 32;
#pragma unroll
        for (int i = 0; i < 4; i++) {
            int idx = tid + i * 256;
            int r   = idx >> 3;
            int c4  = (idx & 7) * 4;
            float4 v = make_float4(0.f, 0.f, 0.f, 0.f);
            if (r < arows)
                v = *(const float4*)&g_agg[(size_t)(row0 + r) * D + kbase + c4];
            uint4 u;
            u.x = f2tf32(v.x); u.y = f2tf32(v.y); u.z = f2tf32(v.z); u.w = f2tf32(v.w);
            *(uint4*)&sA[r * SA_STRIDE + c4] = u;
        }
#pragma unroll
        for (int i = 0; i < 4; i++) {
            int idx = tid + i * 256;
            int kr  = idx >> 5;
            int c4  = (idx & 31) * 4;
            uint4 u = *(const uint4*)&g_wt32[(size_t)(kbase + kr) * D + n0 + c4];
            *(uint4*)&sB[kr * SB_STRIDE + c4] = u;
        }
        __syncthreads();

#pragma unroll
        for (int ks = 0; ks < 4; ks++) {
            const int k0 = ks * 8;
            uint32_t af[4][4], bf[4][2];
#pragma unroll
            for (int mf = 0; mf < 4; mf++) {
                int mrow = wm * 64 + mf * 16 + g;
                const uint32_t* base = &sA[mrow * SA_STRIDE + k0 + t];
                af[mf][0] = base[0];
                af[mf][1] = base[8 * SA_STRIDE];
                af[mf][2] = base[4];
                af[mf][3] = base[8 * SA_STRIDE + 4];
            }
#pragma unroll
            for (int nf = 0; nf < 4; nf++) {
                int ncol = wn * 32 + nf * 8 + g;
                bf[nf][0] = sB[(k0 + t) * SB_STRIDE + ncol];
                bf[nf][1] = sB[(k0 + t + 4) * SB_STRIDE + ncol];
            }
#pragma unroll
            for (int mf = 0; mf < 4; mf++)
#pragma unroll
                for (int nf = 0; nf < 4; nf++)
                    mma_tf32(acc[mf][nf], af[mf], bf[nf]);
        }
        __syncthreads();
    }

#pragma unroll
    for (int mf = 0; mf < 4; mf++) {
        int r0 = row0 + wm * 64 + mf * 16 + g;
        int r1 = r0 + 8;
        float post0 = 0.f, post1 = 0.f;
        if (r0 < n) post0 = rsqrtf(fmaxf((float)g_in_deg[r0], 1.f));
        if (r1 < n) post1 = rsqrtf(fmaxf((float)g_in_deg[r1], 1.f));
#pragma unroll
        for (int nf = 0; nf < 4; nf++) {
            int c = n0 + wn * 32 + nf * 8 + t * 2;
            float2 b2 = *(const float2*)&bias[c];
            if (r0 < n) {
                float2 v;
                v.x = acc[mf][nf][0] * post0 + b2.x;
                v.y = acc[mf][nf][1] * post0 + b2.y;
                *(float2*)&out[(size_t)r0 * D + c] = v;
            }
            if (r1 < n) {
                float2 v;
                v.x = acc[mf][nf][2] * post1 + b2.x;
                v.y = acc[mf][nf][3] * post1 + b2.y;
                *(float2*)&out[(size_t)r1 * D + c] = v;
            }
        }
    }
}

// ======================= launch =======================
extern "C" void kernel_launch(void* const* d_in, const int* in_sizes, int n_in,
                              void* d_out, int out_size) {
    const float* feat   = (const float*)d_in[0];
    const int*   src    = (const int*)d_in[1];
    const int*   dst    = (const int*)d_in[2];
    const float* weight = (const float*)d_in[3];
    const float* bias   = (const float*)d_in[4];
    float*       out    = (float*)d_out;

    int n = in_sizes[0] / D;   // 100000
    int e = in_sizes[1];       // 1600000

    k_zero<<<(n + 255) / 256, 256>>>(n);
    k_deg<<<(e + 255) / 256, 256>>>(src, dst, e);
    k_pre<<<(n + 255) / 256, 256>>>(n);
    k_feat16<<<(n * 32 + 255) / 256, 256>>>((const float4*)feat, n);
    k_wcvt<<<(D * D + 255) / 256, 256>>>(weight);

    int nb = (n + 1023) / 1024;
    k_scan_local<<<nb, 1024>>>(n);
    k_scan_blk<<<1, 128>>>(nb);
    k_scan_add<<<(n + 255) / 256, 256>>>(n);

    k_fill<<<(e + 255) / 256, 256>>>(src, dst, e);

    k_agg<<<(n + 7) / 8, 256>>>(n);

    dim3 gg(2, (n + 127) / 128);
    k_gemm_mma<<<gg, 256>>>(bias, out, n);
}

// round 5
// speedup vs baseline: 2.1371x; 1.0221x over previous
#include <cuda_runtime.h>
#include <cuda_fp16.h>
#include <cstdint>

#define N_MAX 100000
#define E_MAX 1600000
#define D 256

// ---- scratch (static device globals; no allocation) ----
__device__ int      g_out_deg[N_MAX];
__device__ int      g_in_deg[N_MAX];
__device__ int      g_row_ptr[N_MAX + 1];
__device__ int      g_fill[N_MAX];
__device__ int      g_csr_src[E_MAX];
__device__ unsigned long long g_scan_state[128];  // (flag<<32)|value for lookback
__device__ float    g_agg[(size_t)N_MAX * D];
__device__ __half   g_feat16[(size_t)N_MAX * D];  // pre-scaled fp16 features
__device__ uint32_t g_wt32[D * D];                // W as tf32 bits, row-major [k][n]

// ======================= setup kernels =======================
__global__ void k_zero(int n) {
    int i = blockIdx.x * blockDim.x + threadIdx.x;
    if (i < n) { g_out_deg[i] = 0; g_in_deg[i] = 0; g_fill[i] = 0; }
    if (i < 128) g_scan_state[i] = 0ULL;
}

__global__ void k_deg(const int* __restrict__ src, const int* __restrict__ dst, int e) {
    int i = blockIdx.x * blockDim.x + threadIdx.x;
    if (i < e) {
        atomicAdd(&g_out_deg[src[i]], 1);
        atomicAdd(&g_in_deg[dst[i]], 1);
    }
}

// feat -> fp16 with out_deg^-0.5 pre-scale fused. One thread per 8 floats.
__global__ void k_feat16(const float4* __restrict__ feat4, int n) {
    int idx = blockIdx.x * blockDim.x + threadIdx.x;
    if (idx >= n * 32) return;
    int node = idx >> 5;
    float p = rsqrtf((float)max(g_out_deg[node], 1));
    float4 v0 = feat4[(size_t)idx * 2];
    float4 v1 = feat4[(size_t)idx * 2 + 1];
    __half2 h[4];
    h[0] = __floats2half2_rn(v0.x * p, v0.y * p);
    h[1] = __floats2half2_rn(v0.z * p, v0.w * p);
    h[2] = __floats2half2_rn(v1.x * p, v1.y * p);
    h[3] = __floats2half2_rn(v1.z * p, v1.w * p);
    *(uint4*)&g_feat16[(size_t)idx * 8] = *(uint4*)h;
}

// single-pass scan of in_deg -> row_ptr (decoupled lookback, 98 blocks all resident)
__global__ void k_scan(int n) {
    __shared__ int s[1024];
    __shared__ int s_prev;
    const int b = blockIdx.x;
    const int i = b * 1024 + threadIdx.x;
    int v = (i < n) ? g_in_deg[i] : 0;
    s[threadIdx.x] = v;
    __syncthreads();
    for (int off = 1; off < 1024; off <<= 1) {
        int t = (threadIdx.x >= off) ? s[threadIdx.x - off] : 0;
        __syncthreads();
        s[threadIdx.x] += t;
        __syncthreads();
    }
    int incl = s[threadIdx.x];
    int total = s[1023];

    if (threadIdx.x == 0) {
        if (b == 0) {
            atomicExch(&g_scan_state[0], (2ULL << 32) | (unsigned)total);
            s_prev = 0;
        } else {
            // publish aggregate (flag 1)
            atomicExch(&g_scan_state[b], (1ULL << 32) | (unsigned)total);
            // lookback
            int sum = 0;
            for (int p = b - 1; p >= 0; p--) {
                unsigned long long w;
                do { w = atomicAdd(&g_scan_state[p], 0ULL); } while ((w >> 32) == 0);
                sum += (int)(unsigned)w;
                if ((w >> 32) == 2) break;
            }
            // publish inclusive prefix (flag 2)
            atomicExch(&g_scan_state[b], (2ULL << 32) | (unsigned)(sum + total));
            s_prev = sum;
        }
    }
    __syncthreads();
    int prev = s_prev;
    if (i < n) g_row_ptr[i + 1] = prev + incl;
    if (i == 0) g_row_ptr[0] = 0;
}

__global__ void k_fill(const int* __restrict__ src, const int* __restrict__ dst, int e) {
    int i = blockIdx.x * blockDim.x + threadIdx.x;
    if (i < e) {
        int d = dst[i];
        int pos = g_row_ptr[d] + atomicAdd(&g_fill[d], 1);
        g_csr_src[pos] = src[i];
    }
}

// convert W to tf32-rounded bit patterns
__global__ void k_wcvt(const float* __restrict__ W) {
    int i = blockIdx.x * blockDim.x + threadIdx.x;
    if (i < D * D) {
        uint32_t u;
        asm("cvt.rna.tf32.f32 %0, %1;" : "=r"(u) : "f"(W[i]));
        g_wt32[i] = u;
    }
}

// ======================= aggregation (fp16 gather, fp32 accumulate) =======================
__device__ __forceinline__ void acc8(float* acc, uint4 u) {
    __half2* h = (__half2*)&u;
    float2 a0 = __half22float2(h[0]);
    float2 a1 = __half22float2(h[1]);
    float2 a2 = __half22float2(h[2]);
    float2 a3 = __half22float2(h[3]);
    acc[0] += a0.x; acc[1] += a0.y;
    acc[2] += a1.x; acc[3] += a1.y;
    acc[4] += a2.x; acc[5] += a2.y;
    acc[6] += a3.x; acc[7] += a3.y;
}

__global__ __launch_bounds__(256) void k_agg(int n) {
    int node = blockIdx.x * 8 + (threadIdx.x >> 5);
    int lane = threadIdx.x & 31;
    if (node >= n) return;
    int beg = g_row_ptr[node];
    int end = g_row_ptr[node + 1];
    const uint4* f = (const uint4*)g_feat16;  // 32 uint4 per row
    float acc[8];
#pragma unroll
    for (int i = 0; i < 8; i++) acc[i] = 0.f;
    int j = beg;
    for (; j + 4 <= end; j += 4) {
        int s0 = g_csr_src[j];
        int s1 = g_csr_src[j + 1];
        int s2 = g_csr_src[j + 2];
        int s3 = g_csr_src[j + 3];
        uint4 u0 = f[(size_t)s0 * 32 + lane];
        uint4 u1 = f[(size_t)s1 * 32 + lane];
        uint4 u2 = f[(size_t)s2 * 32 + lane];
        uint4 u3 = f[(size_t)s3 * 32 + lane];
        acc8(acc, u0);
        acc8(acc, u1);
        acc8(acc, u2);
        acc8(acc, u3);
    }
    for (; j < end; j++) {
        int s0 = g_csr_src[j];
        uint4 u0 = f[(size_t)s0 * 32 + lane];
        acc8(acc, u0);
    }
    float* o = &g_agg[(size_t)node * D + lane * 8];
    *(float4*)(o + 0) = make_float4(acc[0], acc[1], acc[2], acc[3]);
    *(float4*)(o + 4) = make_float4(acc[4], acc[5], acc[6], acc[7]);
}

// ======================= tf32 warp-MMA GEMM =======================
#define SA_STRIDE 36
#define SB_STRIDE 136

__device__ __forceinline__ void mma_tf32(float* c, const uint32_t* a, const uint32_t* b) {
    asm volatile(
        "mma.sync.aligned.m16n8k8.row.col.f32.tf32.tf32.f32 "
        "{%0,%1,%2,%3}, {%4,%5,%6,%7}, {%8,%9}, {%0,%1,%2,%3};"
        : "+f"(c[0]), "+f"(c[1]), "+f"(c[2]), "+f"(c[3])
        : "r"(a[0]), "r"(a[1]), "r"(a[2]), "r"(a[3]), "r"(b[0]), "r"(b[1]));
}

__device__ __forceinline__ uint32_t f2tf32(float f) {
    uint32_t u;
    asm("cvt.rna.tf32.f32 %0, %1;" : "=r"(u) : "f"(f));
    return u;
}

__global__ __launch_bounds__(256, 2) void k_gemm_mma(const float* __restrict__ bias,
                                                     float* __restrict__ out, int n) {
    __shared__ uint32_t sA[128 * SA_STRIDE];
    __shared__ uint32_t sB[32 * SB_STRIDE];

    const int tid = threadIdx.x;
    const int wid = tid >> 5;
    const int lid = tid & 31;
    const int g   = lid >> 2;
    const int t   = lid & 3;
    const int wm  = wid & 1;
    const int wn  = wid >> 1;

    const int row0 = blockIdx.y * 128;
    const int n0   = blockIdx.x * 128;
    const int arows = min(128, n - row0);

    float acc[4][4][4];
#pragma unroll
    for (int mf = 0; mf < 4; mf++)
#pragma unroll
        for (int nf = 0; nf < 4; nf++)
#pragma unroll
            for (int r = 0; r < 4; r++) acc[mf][nf][r] = 0.f;

    for (int kc = 0; kc < 8; kc++) {
        const int kbase = kc * 32;
#pragma unroll
        for (int i = 0; i < 4; i++) {
            int idx = tid + i * 256;
            int r   = idx >> 3;
            int c4  = (idx & 7) * 4;
            float4 v = make_float4(0.f, 0.f, 0.f, 0.f);
            if (r < arows)
                v = *(const float4*)&g_agg[(size_t)(row0 + r) * D + kbase + c4];
            uint4 u;
            u.x = f2tf32(v.x); u.y = f2tf32(v.y); u.z = f2tf32(v.z); u.w = f2tf32(v.w);
            *(uint4*)&sA[r * SA_STRIDE + c4] = u;
        }
#pragma unroll
        for (int i = 0; i < 4; i++) {
            int idx = tid + i * 256;
            int kr  = idx >> 5;
            int c4  = (idx & 31) * 4;
            uint4 u = *(const uint4*)&g_wt32[(size_t)(kbase + kr) * D + n0 + c4];
            *(uint4*)&sB[kr * SB_STRIDE + c4] = u;
        }
        __syncthreads();

#pragma unroll
        for (int ks = 0; ks < 4; ks++) {
            const int k0 = ks * 8;
            uint32_t af[4][4], bf[4][2];
#pragma unroll
            for (int mf = 0; mf < 4; mf++) {
                int mrow = wm * 64 + mf * 16 + g;
                const uint32_t* base = &sA[mrow * SA_STRIDE + k0 + t];
                af[mf][0] = base[0];
                af[mf][1] = base[8 * SA_STRIDE];
                af[mf][2] = base[4];
                af[mf][3] = base[8 * SA_STRIDE + 4];
            }
#pragma unroll
            for (int nf = 0; nf < 4; nf++) {
                int ncol = wn * 32 + nf * 8 + g;
                bf[nf][0] = sB[(k0 + t) * SB_STRIDE + ncol];
                bf[nf][1] = sB[(k0 + t + 4) * SB_STRIDE + ncol];
            }
#pragma unroll
            for (int mf = 0; mf < 4; mf++)
#pragma unroll
                for (int nf = 0; nf < 4; nf++)
                    mma_tf32(acc[mf][nf], af[mf], bf[nf]);
        }
        __syncthreads();
    }

#pragma unroll
    for (int mf = 0; mf < 4; mf++) {
        int r0 = row0 + wm * 64 + mf * 16 + g;
        int r1 = r0 + 8;
        float post0 = 0.f, post1 = 0.f;
        if (r0 < n) post0 = rsqrtf(fmaxf((float)g_in_deg[r0], 1.f));
        if (r1 < n) post1 = rsqrtf(fmaxf((float)g_in_deg[r1], 1.f));
#pragma unroll
        for (int nf = 0; nf < 4; nf++) {
            int c = n0 + wn * 32 + nf * 8 + t * 2;
            float2 b2 = *(const float2*)&bias[c];
            if (r0 < n) {
                float2 v;
                v.x = acc[mf][nf][0] * post0 + b2.x;
                v.y = acc[mf][nf][1] * post0 + b2.y;
                *(float2*)&out[(size_t)r0 * D + c] = v;
            }
            if (r1 < n) {
                float2 v;
                v.x = acc[mf][nf][2] * post1 + b2.x;
                v.y = acc[mf][nf][3] * post1 + b2.y;
                *(float2*)&out[(size_t)r1 * D + c] = v;
            }
        }
    }
}

// ======================= launch =======================
extern "C" void kernel_launch(void* const* d_in, const int* in_sizes, int n_in,
                              void* d_out, int out_size) {
    const float* feat   = (const float*)d_in[0];
    const int*   src    = (const int*)d_in[1];
    const int*   dst    = (const int*)d_in[2];
    const float* weight = (const float*)d_in[3];
    const float* bias   = (const float*)d_in[4];
    float*       out    = (float*)d_out;

    int n = in_sizes[0] / D;   // 100000
    int e = in_sizes[1];       // 1600000

    // launch order tuned so ncu (-s 5 -c 1) profiles k_agg
    k_zero<<<(n + 255) / 256, 256>>>(n);                       // 0
    k_deg<<<(e + 255) / 256, 256>>>(src, dst, e);              // 1
    k_feat16<<<(n * 32 + 255) / 256, 256>>>((const float4*)feat, n);  // 2
    int nb = (n + 1023) / 1024;
    k_scan<<<nb, 1024>>>(n);                                   // 3
    k_fill<<<(e + 255) / 256, 256>>>(src, dst, e);             // 4
    k_agg<<<(n + 7) / 8, 256>>>(n);                            // 5  <- profiled
    k_wcvt<<<(D * D + 255) / 256, 256>>>(weight);              // 6
    dim3 gg(2, (n + 127) / 128);
    k_gemm_mma<<<gg, 256>>>(bias, out, n);                     // 7
}

// round 6
// speedup vs baseline: 2.6587x; 1.2440x over previous
#include <cuda_runtime.h>
#include <cuda_fp16.h>
#include <cstdint>

#define N_MAX 100000
#define E_MAX 1600000
#define D 256

// ---- scratch (static device globals; zero-initialized at load, re-zeroed at tail) ----
__device__ int      g_out_deg[N_MAX];
__device__ int      g_in_deg[N_MAX];
__device__ int      g_row_ptr[N_MAX + 1];
__device__ int      g_fill[N_MAX];
__device__ int      g_csr_src[E_MAX];
__device__ unsigned long long g_scan_state[128];  // (flag<<32)|value for lookback
__device__ __half   g_agg16[(size_t)N_MAX * D];   // aggregated features, fp16
__device__ __half   g_feat16[(size_t)N_MAX * D];  // pre-scaled fp16 features
__device__ __half   g_wt16[D * D];                // W^T as fp16, [n][k]

// ======================= setup kernels =======================
__global__ void k_deg(const int* __restrict__ src, const int* __restrict__ dst, int e) {
    int i = blockIdx.x * blockDim.x + threadIdx.x;
    if (i < e) {
        atomicAdd(&g_out_deg[src[i]], 1);
        atomicAdd(&g_in_deg[dst[i]], 1);
    }
}

// single-pass scan of in_deg -> row_ptr (decoupled lookback, 98 blocks all resident)
__global__ void k_scan(int n) {
    __shared__ int s[1024];
    __shared__ int s_prev;
    const int b = blockIdx.x;
    const int i = b * 1024 + threadIdx.x;
    int v = (i < n) ? g_in_deg[i] : 0;
    s[threadIdx.x] = v;
    __syncthreads();
    for (int off = 1; off < 1024; off <<= 1) {
        int t = (threadIdx.x >= off) ? s[threadIdx.x - off] : 0;
        __syncthreads();
        s[threadIdx.x] += t;
        __syncthreads();
    }
    int incl = s[threadIdx.x];
    int total = s[1023];

    if (threadIdx.x == 0) {
        if (b == 0) {
            atomicExch(&g_scan_state[0], (2ULL << 32) | (unsigned)total);
            s_prev = 0;
        } else {
            atomicExch(&g_scan_state[b], (1ULL << 32) | (unsigned)total);
            int sum = 0;
            for (int p = b - 1; p >= 0; p--) {
                unsigned long long w;
                do { w = atomicAdd(&g_scan_state[p], 0ULL); } while ((w >> 32) == 0);
                sum += (int)(unsigned)w;
                if ((w >> 32) == 2) break;
            }
            atomicExch(&g_scan_state[b], (2ULL << 32) | (unsigned)(sum + total));
            s_prev = sum;
        }
    }
    __syncthreads();
    int prev = s_prev;
    if (i < n) g_row_ptr[i + 1] = prev + incl;
    if (i == 0) g_row_ptr[0] = 0;
}

// fused: CSR fill (threads < e) + feat->fp16 pre-scaled convert (threads < n*32)
__global__ void k_fill_feat(const int* __restrict__ src, const int* __restrict__ dst,
                            const float4* __restrict__ feat4, int e, int n) {
    int i = blockIdx.x * blockDim.x + threadIdx.x;
    if (i < e) {
        int d = dst[i];
        int pos = g_row_ptr[d] + atomicAdd(&g_fill[d], 1);
        g_csr_src[pos] = src[i];
    }
    if (i < n * 32) {
        int node = i >> 5;
        float p = rsqrtf((float)max(g_out_deg[node], 1));
        float4 v0 = feat4[(size_t)i * 2];
        float4 v1 = feat4[(size_t)i * 2 + 1];
        __half2 h[4];
        h[0] = __floats2half2_rn(v0.x * p, v0.y * p);
        h[1] = __floats2half2_rn(v0.z * p, v0.w * p);
        h[2] = __floats2half2_rn(v1.x * p, v1.y * p);
        h[3] = __floats2half2_rn(v1.z * p, v1.w * p);
        *(uint4*)&g_feat16[(size_t)i * 8] = *(uint4*)h;
    }
}

// W[k][n] fp32 -> g_wt16[n][k] fp16 (transpose + convert)
__global__ void k_wcvt(const float* __restrict__ W) {
    __shared__ float t[32][33];
    int bx = blockIdx.x & 7, by = blockIdx.x >> 3;
    int x  = bx * 32 + threadIdx.x;   // n
    int y0 = by * 32 + threadIdx.y;   // k
    for (int i = 0; i < 32; i += 8)
        t[threadIdx.y + i][threadIdx.x] = W[(size_t)(y0 + i) * D + x];
    __syncthreads();
    int on  = bx * 32 + threadIdx.y;  // n (output row)
    int ok  = by * 32 + threadIdx.x;  // k (output col)
    for (int i = 0; i < 32; i += 8)
        g_wt16[(size_t)(on + i) * D + ok] = __float2half_rn(t[threadIdx.x][threadIdx.y + i]);
}

// ======================= aggregation (fp16 gather, fp32 accumulate, fp16 out) =======================
__device__ __forceinline__ void acc8(float* acc, uint4 u) {
    __half2* h = (__half2*)&u;
    float2 a0 = __half22float2(h[0]);
    float2 a1 = __half22float2(h[1]);
    float2 a2 = __half22float2(h[2]);
    float2 a3 = __half22float2(h[3]);
    acc[0] += a0.x; acc[1] += a0.y;
    acc[2] += a1.x; acc[3] += a1.y;
    acc[4] += a2.x; acc[5] += a2.y;
    acc[6] += a3.x; acc[7] += a3.y;
}

__global__ __launch_bounds__(256) void k_agg(int n) {
    int node = blockIdx.x * 8 + (threadIdx.x >> 5);
    int lane = threadIdx.x & 31;
    if (node >= n) return;
    int beg = g_row_ptr[node];
    int end = g_row_ptr[node + 1];
    const uint4* f = (const uint4*)g_feat16;  // 32 uint4 per row
    float acc[8];
#pragma unroll
    for (int i = 0; i < 8; i++) acc[i] = 0.f;
    int j = beg;
    for (; j + 4 <= end; j += 4) {
        int s0 = g_csr_src[j];
        int s1 = g_csr_src[j + 1];
        int s2 = g_csr_src[j + 2];
        int s3 = g_csr_src[j + 3];
        uint4 u0 = f[(size_t)s0 * 32 + lane];
        uint4 u1 = f[(size_t)s1 * 32 + lane];
        uint4 u2 = f[(size_t)s2 * 32 + lane];
        uint4 u3 = f[(size_t)s3 * 32 + lane];
        acc8(acc, u0);
        acc8(acc, u1);
        acc8(acc, u2);
        acc8(acc, u3);
    }
    for (; j < end; j++) {
        int s0 = g_csr_src[j];
        uint4 u0 = f[(size_t)s0 * 32 + lane];
        acc8(acc, u0);
    }
    __half2 h[4];
    h[0] = __floats2half2_rn(acc[0], acc[1]);
    h[1] = __floats2half2_rn(acc[2], acc[3]);
    h[2] = __floats2half2_rn(acc[4], acc[5]);
    h[3] = __floats2half2_rn(acc[6], acc[7]);
    *(uint4*)&g_agg16[(size_t)node * D + lane * 8] = *(uint4*)h;
}

// ======================= fp16 warp-MMA GEMM =======================
// C[n,256] = agg16[n,256] @ W, fused post-scale + bias.
// CTA 128x128, 8 warps (2m x 4n), warp 64x32 = 4x4 m16n8k16 frags.
// sA: [m][k] halves stride 40; sB: [n][k] halves stride 40.
#define SAB_STRIDE 40

__device__ __forceinline__ void mma_f16(float* c, const uint32_t* a, const uint32_t* b) {
    asm volatile(
        "mma.sync.aligned.m16n8k16.row.col.f32.f16.f16.f32 "
        "{%0,%1,%2,%3}, {%4,%5,%6,%7}, {%8,%9}, {%0,%1,%2,%3};"
        : "+f"(c[0]), "+f"(c[1]), "+f"(c[2]), "+f"(c[3])
        : "r"(a[0]), "r"(a[1]), "r"(a[2]), "r"(a[3]), "r"(b[0]), "r"(b[1]));
}

__global__ __launch_bounds__(256, 2) void k_gemm_mma(const float* __restrict__ bias,
                                                     float* __restrict__ out, int n) {
    __shared__ __half sA[128 * SAB_STRIDE];
    __shared__ __half sB[128 * SAB_STRIDE];

    const int tid = threadIdx.x;
    const int wid = tid >> 5;
    const int lid = tid & 31;
    const int g   = lid >> 2;
    const int t   = lid & 3;
    const int wm  = wid & 1;
    const int wn  = wid >> 1;

    const int row0 = blockIdx.y * 128;
    const int n0   = blockIdx.x * 128;
    const int arows = min(128, n - row0);

    float acc[4][4][4];
#pragma unroll
    for (int mf = 0; mf < 4; mf++)
#pragma unroll
        for (int nf = 0; nf < 4; nf++)
#pragma unroll
            for (int r = 0; r < 4; r++) acc[mf][nf][r] = 0.f;

    for (int kc = 0; kc < 8; kc++) {
        const int kbase = kc * 32;
        // stage A: 128 rows x 32 halves (4 uint4/row), 2 uint4/thread
#pragma unroll
        for (int i = 0; i < 2; i++) {
            int idx = tid + i * 256;
            int r   = idx >> 2;
            int c8  = (idx & 3) * 8;
            uint4 u = make_uint4(0, 0, 0, 0);
            if (r < arows)
                u = *(const uint4*)&g_agg16[(size_t)(row0 + r) * D + kbase + c8];
            *(uint4*)&sA[r * SAB_STRIDE + c8] = u;
        }
        // stage B: 128 n-rows x 32 halves from W^T[n][k]
#pragma unroll
        for (int i = 0; i < 2; i++) {
            int idx = tid + i * 256;
            int nn  = idx >> 2;
            int c8  = (idx & 3) * 8;
            uint4 u = *(const uint4*)&g_wt16[(size_t)(n0 + nn) * D + kbase + c8];
            *(uint4*)&sB[nn * SAB_STRIDE + c8] = u;
        }
        __syncthreads();

#pragma unroll
        for (int ks = 0; ks < 2; ks++) {
            const int k0 = ks * 16;
            uint32_t af[4][4], bf[4][2];
#pragma unroll
            for (int mf = 0; mf < 4; mf++) {
                int mrow = wm * 64 + mf * 16 + g;
                const __half* base = &sA[mrow * SAB_STRIDE + k0 + 2 * t];
                af[mf][0] = *(const uint32_t*)(base);
                af[mf][1] = *(const uint32_t*)(base + 8 * SAB_STRIDE);
                af[mf][2] = *(const uint32_t*)(base + 8);
                af[mf][3] = *(const uint32_t*)(base + 8 * SAB_STRIDE + 8);
            }
#pragma unroll
            for (int nf = 0; nf < 4; nf++) {
                int ncol = wn * 32 + nf * 8 + g;
                const __half* base = &sB[ncol * SAB_STRIDE + k0 + 2 * t];
                bf[nf][0] = *(const uint32_t*)(base);
                bf[nf][1] = *(const uint32_t*)(base + 8);
            }
#pragma unroll
            for (int mf = 0; mf < 4; mf++)
#pragma unroll
                for (int nf = 0; nf < 4; nf++)
                    mma_f16(acc[mf][nf], af[mf], bf[nf]);
        }
        __syncthreads();
    }

#pragma unroll
    for (int mf = 0; mf < 4; mf++) {
        int r0 = row0 + wm * 64 + mf * 16 + g;
        int r1 = r0 + 8;
        float post0 = 0.f, post1 = 0.f;
        if (r0 < n) post0 = rsqrtf(fmaxf((float)g_in_deg[r0], 1.f));
        if (r1 < n) post1 = rsqrtf(fmaxf((float)g_in_deg[r1], 1.f));
#pragma unroll
        for (int nf = 0; nf < 4; nf++) {
            int c = n0 + wn * 32 + nf * 8 + t * 2;
            float2 b2 = *(const float2*)&bias[c];
            if (r0 < n) {
                float2 v;
                v.x = acc[mf][nf][0] * post0 + b2.x;
                v.y = acc[mf][nf][1] * post0 + b2.y;
                *(float2*)&out[(size_t)r0 * D + c] = v;
            }
            if (r1 < n) {
                float2 v;
                v.x = acc[mf][nf][2] * post1 + b2.x;
                v.y = acc[mf][nf][3] * post1 + b2.y;
                *(float2*)&out[(size_t)r1 * D + c] = v;
            }
        }
    }
}

// zero scratch counters for the NEXT invocation (globals start zeroed at load)
__global__ void k_zero_tail(int n) {
    int i = blockIdx.x * blockDim.x + threadIdx.x;
    if (i < n) { g_out_deg[i] = 0; g_in_deg[i] = 0; g_fill[i] = 0; }
    if (i < 128) g_scan_state[i] = 0ULL;
}

// ======================= launch =======================
extern "C" void kernel_launch(void* const* d_in, const int* in_sizes, int n_in,
                              void* d_out, int out_size) {
    const float* feat   = (const float*)d_in[0];
    const int*   src    = (const int*)d_in[1];
    const int*   dst    = (const int*)d_in[2];
    const float* weight = (const float*)d_in[3];
    const float* bias   = (const float*)d_in[4];
    float*       out    = (float*)d_out;

    int n = in_sizes[0] / D;   // 100000
    int e = in_sizes[1];       // 1600000

    int nb = (n + 1023) / 1024;
    int fused_threads = (n * 32 > e) ? n * 32 : e;

    k_deg<<<(e + 255) / 256, 256>>>(src, dst, e);                       // 0
    k_scan<<<nb, 1024>>>(n);                                            // 1
    k_fill_feat<<<(fused_threads + 255) / 256, 256>>>(src, dst,
                                       (const float4*)feat, e, n);      // 2
    k_agg<<<(n + 7) / 8, 256>>>(n);                                     // 3  <- profiled
    k_wcvt<<<64, dim3(32, 8)>>>(weight);                                // 4
    dim3 gg(2, (n + 127) / 128);
    k_gemm_mma<<<gg, 256>>>(bias, out, n);                              // 5
    k_zero_tail<<<(n + 255) / 256, 256>>>(n);                           // 6
}

// round 7
// speedup vs baseline: 2.6773x; 1.0070x over previous
#include <cuda_runtime.h>
#include <cuda_fp16.h>
#include <cstdint>

#define N_MAX 100000
#define E_MAX 1600000
#define D 256

// ---- scratch (static device globals; zero-initialized at load, re-zeroed at tail) ----
__device__ int      g_out_deg[N_MAX];
__device__ int      g_in_deg[N_MAX];
__device__ int      g_row_ptr[N_MAX + 1];
__device__ int      g_fill[N_MAX];
__device__ int      g_csr_src[E_MAX];
__device__ unsigned long long g_scan_state[128];  // (flag<<32)|value for lookback
__device__ __half   g_agg16[(size_t)N_MAX * D];   // aggregated features, fp16
__device__ __half   g_feat16[(size_t)N_MAX * D];  // pre-scaled fp16 features
__device__ __half   g_wt16[D * D];                // W^T as fp16, [n][k]

// ======================= setup kernels =======================
__global__ void k_deg(const int* __restrict__ src, const int* __restrict__ dst, int e) {
    int i = blockIdx.x * blockDim.x + threadIdx.x;
    if (i < e) {
        atomicAdd(&g_out_deg[src[i]], 1);
        atomicAdd(&g_in_deg[dst[i]], 1);
    }
}

// single-pass scan of in_deg -> row_ptr (decoupled lookback, 98 blocks all resident)
__global__ void k_scan(int n) {
    __shared__ int s[1024];
    __shared__ int s_prev;
    const int b = blockIdx.x;
    const int i = b * 1024 + threadIdx.x;
    int v = (i < n) ? g_in_deg[i] : 0;
    s[threadIdx.x] = v;
    __syncthreads();
    for (int off = 1; off < 1024; off <<= 1) {
        int t = (threadIdx.x >= off) ? s[threadIdx.x - off] : 0;
        __syncthreads();
        s[threadIdx.x] += t;
        __syncthreads();
    }
    int incl = s[threadIdx.x];
    int total = s[1023];

    if (threadIdx.x == 0) {
        if (b == 0) {
            atomicExch(&g_scan_state[0], (2ULL << 32) | (unsigned)total);
            s_prev = 0;
        } else {
            atomicExch(&g_scan_state[b], (1ULL << 32) | (unsigned)total);
            int sum = 0;
            for (int p = b - 1; p >= 0; p--) {
                unsigned long long w;
                do { w = atomicAdd(&g_scan_state[p], 0ULL); } while ((w >> 32) == 0);
                sum += (int)(unsigned)w;
                if ((w >> 32) == 2) break;
            }
            atomicExch(&g_scan_state[b], (2ULL << 32) | (unsigned)(sum + total));
            s_prev = sum;
        }
    }
    __syncthreads();
    int prev = s_prev;
    if (i < n) g_row_ptr[i + 1] = prev + incl;
    if (i == 0) g_row_ptr[0] = 0;
}

// fused: CSR fill (threads < e) + feat->fp16 pre-scaled convert (threads < n*32)
__global__ void k_fill_feat(const int* __restrict__ src, const int* __restrict__ dst,
                            const float4* __restrict__ feat4, int e, int n) {
    int i = blockIdx.x * blockDim.x + threadIdx.x;
    if (i < e) {
        int d = dst[i];
        int pos = g_row_ptr[d] + atomicAdd(&g_fill[d], 1);
        g_csr_src[pos] = src[i];
    }
    if (i < n * 32) {
        int node = i >> 5;
        float p = rsqrtf((float)max(g_out_deg[node], 1));
        float4 v0 = feat4[(size_t)i * 2];
        float4 v1 = feat4[(size_t)i * 2 + 1];
        __half2 h[4];
        h[0] = __floats2half2_rn(v0.x * p, v0.y * p);
        h[1] = __floats2half2_rn(v0.z * p, v0.w * p);
        h[2] = __floats2half2_rn(v1.x * p, v1.y * p);
        h[3] = __floats2half2_rn(v1.z * p, v1.w * p);
        *(uint4*)&g_feat16[(size_t)i * 8] = *(uint4*)h;
    }
}

// W[k][n] fp32 -> g_wt16[n][k] fp16 (transpose + convert)
__global__ void k_wcvt(const float* __restrict__ W) {
    __shared__ float t[32][33];
    int bx = blockIdx.x & 7, by = blockIdx.x >> 3;
    int x  = bx * 32 + threadIdx.x;   // n
    int y0 = by * 32 + threadIdx.y;   // k
    for (int i = 0; i < 32; i += 8)
        t[threadIdx.y + i][threadIdx.x] = W[(size_t)(y0 + i) * D + x];
    __syncthreads();
    int on  = bx * 32 + threadIdx.y;  // n (output row)
    int ok  = by * 32 + threadIdx.x;  // k (output col)
    for (int i = 0; i < 32; i += 8)
        g_wt16[(size_t)(on + i) * D + ok] = __float2half_rn(t[threadIdx.x][threadIdx.y + i]);
}

// ======================= aggregation =======================
// fp16 gather; pairwise fp16 edge-sum, then packed f32x2 accumulate.
__device__ __forceinline__ unsigned long long pack_f2(float2 f) {
    unsigned long long r;
    asm("mov.b64 %0, {%1, %2};" : "=l"(r) : "f"(f.x), "f"(f.y));
    return r;
}

__device__ __forceinline__ void accpair(unsigned long long* acc, uint4 u0, uint4 u1) {
    __half2* h0 = (__half2*)&u0;
    __half2* h1 = (__half2*)&u1;
#pragma unroll
    for (int i = 0; i < 4; i++) {
        __half2 p = __hadd2(h0[i], h1[i]);
        float2 fp = __half22float2(p);
        asm("add.rn.f32x2 %0, %0, %1;" : "+l"(acc[i]) : "l"(pack_f2(fp)));
    }
}

__device__ __forceinline__ void accone(unsigned long long* acc, uint4 u0) {
    __half2* h0 = (__half2*)&u0;
#pragma unroll
    for (int i = 0; i < 4; i++) {
        float2 fp = __half22float2(h0[i]);
        asm("add.rn.f32x2 %0, %0, %1;" : "+l"(acc[i]) : "l"(pack_f2(fp)));
    }
}

__global__ __launch_bounds__(256) void k_agg(int n) {
    int node = blockIdx.x * 8 + (threadIdx.x >> 5);
    int lane = threadIdx.x & 31;
    if (node >= n) return;
    int beg = g_row_ptr[node];
    int end = g_row_ptr[node + 1];
    const uint4* f = (const uint4*)g_feat16;  // 32 uint4 per row
    unsigned long long acc[4] = {0ULL, 0ULL, 0ULL, 0ULL};  // 8 packed fp32
    int j = beg;
    for (; j + 4 <= end; j += 4) {
        int s0 = g_csr_src[j];
        int s1 = g_csr_src[j + 1];
        int s2 = g_csr_src[j + 2];
        int s3 = g_csr_src[j + 3];
        uint4 u0 = f[(size_t)s0 * 32 + lane];
        uint4 u1 = f[(size_t)s1 * 32 + lane];
        uint4 u2 = f[(size_t)s2 * 32 + lane];
        uint4 u3 = f[(size_t)s3 * 32 + lane];
        accpair(acc, u0, u1);
        accpair(acc, u2, u3);
    }
    if (j + 2 <= end) {
        int s0 = g_csr_src[j];
        int s1 = g_csr_src[j + 1];
        uint4 u0 = f[(size_t)s0 * 32 + lane];
        uint4 u1 = f[(size_t)s1 * 32 + lane];
        accpair(acc, u0, u1);
        j += 2;
    }
    if (j < end) {
        int s0 = g_csr_src[j];
        accone(acc, f[(size_t)s0 * 32 + lane]);
    }
    __half2 h[4];
#pragma unroll
    for (int i = 0; i < 4; i++) {
        float lo, hi;
        asm("mov.b64 {%0, %1}, %2;" : "=f"(lo), "=f"(hi) : "l"(acc[i]));
        h[i] = __floats2half2_rn(lo, hi);
    }
    *(uint4*)&g_agg16[(size_t)node * D + lane * 8] = *(uint4*)h;
}

// ======================= fp16 warp-MMA GEMM (double-buffered) =======================
#define SAB_STRIDE 40

__device__ __forceinline__ void mma_f16(float* c, const uint32_t* a, const uint32_t* b) {
    asm volatile(
        "mma.sync.aligned.m16n8k16.row.col.f32.f16.f16.f32 "
        "{%0,%1,%2,%3}, {%4,%5,%6,%7}, {%8,%9}, {%0,%1,%2,%3};"
        : "+f"(c[0]), "+f"(c[1]), "+f"(c[2]), "+f"(c[3])
        : "r"(a[0]), "r"(a[1]), "r"(a[2]), "r"(a[3]), "r"(b[0]), "r"(b[1]));
}

__global__ __launch_bounds__(256, 2) void k_gemm_mma(const float* __restrict__ bias,
                                                     float* __restrict__ out, int n) {
    __shared__ __half sA[2][128 * SAB_STRIDE];
    __shared__ __half sB[2][128 * SAB_STRIDE];

    const int tid = threadIdx.x;
    const int wid = tid >> 5;
    const int lid = tid & 31;
    const int g   = lid >> 2;
    const int t   = lid & 3;
    const int wm  = wid & 1;
    const int wn  = wid >> 1;

    const int row0 = blockIdx.y * 128;
    const int n0   = blockIdx.x * 128;
    const int arows = min(128, n - row0);

    // per-thread staging coords: 2 uint4 per array
    const int st_r  = tid >> 2;          // 0..63 (+64 for second)
    const int st_c8 = (tid & 3) * 8;

    float acc[4][4][4];
#pragma unroll
    for (int mf = 0; mf < 4; mf++)
#pragma unroll
        for (int nf = 0; nf < 4; nf++)
#pragma unroll
            for (int r = 0; r < 4; r++) acc[mf][nf][r] = 0.f;

    uint4 ua[2], ub[2];
    // prologue: load chunk 0
#pragma unroll
    for (int i = 0; i < 2; i++) {
        int r = st_r + i * 64;
        ua[i] = make_uint4(0, 0, 0, 0);
        if (r < arows) ua[i] = *(const uint4*)&g_agg16[(size_t)(row0 + r) * D + st_c8];
        ub[i] = *(const uint4*)&g_wt16[(size_t)(n0 + r) * D + st_c8];
    }
#pragma unroll
    for (int i = 0; i < 2; i++) {
        int r = st_r + i * 64;
        *(uint4*)&sA[0][r * SAB_STRIDE + st_c8] = ua[i];
        *(uint4*)&sB[0][r * SAB_STRIDE + st_c8] = ub[i];
    }
    __syncthreads();

    for (int kc = 0; kc < 8; kc++) {
        const int cur = kc & 1;
        // prefetch next chunk to regs
        if (kc < 7) {
            const int kb = (kc + 1) * 32;
#pragma unroll
            for (int i = 0; i < 2; i++) {
                int r = st_r + i * 64;
                ua[i] = make_uint4(0, 0, 0, 0);
                if (r < arows) ua[i] = *(const uint4*)&g_agg16[(size_t)(row0 + r) * D + kb + st_c8];
                ub[i] = *(const uint4*)&g_wt16[(size_t)(n0 + r) * D + kb + st_c8];
            }
        }
        // compute from cur
#pragma unroll
        for (int ks = 0; ks < 2; ks++) {
            const int k0 = ks * 16;
            uint32_t af[4][4], bf[4][2];
#pragma unroll
            for (int mf = 0; mf < 4; mf++) {
                int mrow = wm * 64 + mf * 16 + g;
                const __half* base = &sA[cur][mrow * SAB_STRIDE + k0 + 2 * t];
                af[mf][0] = *(const uint32_t*)(base);
                af[mf][1] = *(const uint32_t*)(base + 8 * SAB_STRIDE);
                af[mf][2] = *(const uint32_t*)(base + 8);
                af[mf][3] = *(const uint32_t*)(base + 8 * SAB_STRIDE + 8);
            }
#pragma unroll
            for (int nf = 0; nf < 4; nf++) {
                int ncol = wn * 32 + nf * 8 + g;
                const __half* base = &sB[cur][ncol * SAB_STRIDE + k0 + 2 * t];
                bf[nf][0] = *(const uint32_t*)(base);
                bf[nf][1] = *(const uint32_t*)(base + 8);
            }
#pragma unroll
            for (int mf = 0; mf < 4; mf++)
#pragma unroll
                for (int nf = 0; nf < 4; nf++)
                    mma_f16(acc[mf][nf], af[mf], bf[nf]);
        }
        // store next chunk, one sync per iter
        if (kc < 7) {
            const int nxt = cur ^ 1;
#pragma unroll
            for (int i = 0; i < 2; i++) {
                int r = st_r + i * 64;
                *(uint4*)&sA[nxt][r * SAB_STRIDE + st_c8] = ua[i];
                *(uint4*)&sB[nxt][r * SAB_STRIDE + st_c8] = ub[i];
            }
            __syncthreads();
        }
    }

#pragma unroll
    for (int mf = 0; mf < 4; mf++) {
        int r0 = row0 + wm * 64 + mf * 16 + g;
        int r1 = r0 + 8;
        float post0 = 0.f, post1 = 0.f;
        if (r0 < n) post0 = rsqrtf(fmaxf((float)g_in_deg[r0], 1.f));
        if (r1 < n) post1 = rsqrtf(fmaxf((float)g_in_deg[r1], 1.f));
#pragma unroll
        for (int nf = 0; nf < 4; nf++) {
            int c = n0 + wn * 32 + nf * 8 + t * 2;
            float2 b2 = *(const float2*)&bias[c];
            if (r0 < n) {
                float2 v;
                v.x = acc[mf][nf][0] * post0 + b2.x;
                v.y = acc[mf][nf][1] * post0 + b2.y;
                *(float2*)&out[(size_t)r0 * D + c] = v;
            }
            if (r1 < n) {
                float2 v;
                v.x = acc[mf][nf][2] * post1 + b2.x;
                v.y = acc[mf][nf][3] * post1 + b2.y;
                *(float2*)&out[(size_t)r1 * D + c] = v;
            }
        }
    }
}

// zero scratch counters for the NEXT invocation (globals start zeroed at load)
__global__ void k_zero_tail(int n) {
    int i = blockIdx.x * blockDim.x + threadIdx.x;
    if (i < n) { g_out_deg[i] = 0; g_in_deg[i] = 0; g_fill[i] = 0; }
    if (i < 128) g_scan_state[i] = 0ULL;
}

// ======================= launch =======================
extern "C" void kernel_launch(void* const* d_in, const int* in_sizes, int n_in,
                              void* d_out, int out_size) {
    const float* feat   = (const float*)d_in[0];
    const int*   src    = (const int*)d_in[1];
    const int*   dst    = (const int*)d_in[2];
    const float* weight = (const float*)d_in[3];
    const float* bias   = (const float*)d_in[4];
    float*       out    = (float*)d_out;

    int n = in_sizes[0] / D;   // 100000
    int e = in_sizes[1];       // 1600000

    int nb = (n + 1023) / 1024;
    int fused_threads = (n * 32 > e) ? n * 32 : e;

    k_deg<<<(e + 255) / 256, 256>>>(src, dst, e);                       // 0
    k_scan<<<nb, 1024>>>(n);                                            // 1
    k_fill_feat<<<(fused_threads + 255) / 256, 256>>>(src, dst,
                                       (const float4*)feat, e, n);      // 2
    k_agg<<<(n + 7) / 8, 256>>>(n);                                     // 3  <- profiled
    k_wcvt<<<64, dim3(32, 8)>>>(weight);                                // 4
    dim3 gg(2, (n + 127) / 128);
    k_gemm_mma<<<gg, 256>>>(bias, out, n);                              // 5
    k_zero_tail<<<(n + 255) / 256, 256>>>(n);                           // 6
}

// round 8
// speedup vs baseline: 2.7925x; 1.0431x over previous
#include <cuda_runtime.h>
#include <cuda_fp16.h>
#include <cstdint>

#define N_MAX 100000
#define E_MAX 1600000
#define D 256

// ---- scratch (static device globals; zero-initialized at load, re-zeroed at tail) ----
__device__ int      g_out_deg[N_MAX];
__device__ int      g_in_deg[N_MAX];
__device__ int      g_row_ptr[N_MAX + 1];
__device__ int      g_fill[N_MAX];
__device__ int      g_csr_src[E_MAX];
__device__ unsigned long long g_scan_state[128];  // (flag<<32)|value for lookback
__device__ __half   g_agg16[(size_t)N_MAX * D];   // aggregated features, fp16
__device__ __half   g_feat16[(size_t)N_MAX * D];  // pre-scaled fp16 features
__device__ __half   g_wt16[D * D];                // W^T as fp16, [n][k]

// ======================= kernels =======================
__global__ void k_deg(const int* __restrict__ src, const int* __restrict__ dst, int e) {
    int i = blockIdx.x * blockDim.x + threadIdx.x;
    if (i < e) {
        atomicAdd(&g_out_deg[src[i]], 1);
        atomicAdd(&g_in_deg[dst[i]], 1);
    }
}

// Fat kernel: blocks [0,nb) = decoupled-lookback scan of in_deg -> row_ptr;
// blocks [nb, nb+fb) = feat -> fp16 pre-scaled convert;
// blocks [nb+fb, nb+fb+64) = W transpose+fp16.
__global__ __launch_bounds__(1024) void k_mid(const float4* __restrict__ feat4,
                                              const float* __restrict__ W,
                                              int n, int nb, int fb) {
    __shared__ int s[1088];   // scan: 1024 ints; wcvt: 32x33 floats + spare
    const int b = blockIdx.x;

    if (b < nb) {
        // ---- scan ----
        __shared__ int s_prev;
        const int i = b * 1024 + threadIdx.x;
        int v = (i < n) ? g_in_deg[i] : 0;
        s[threadIdx.x] = v;
        __syncthreads();
        for (int off = 1; off < 1024; off <<= 1) {
            int t = (threadIdx.x >= off) ? s[threadIdx.x - off] : 0;
            __syncthreads();
            s[threadIdx.x] += t;
            __syncthreads();
        }
        int incl = s[threadIdx.x];
        int total = s[1023];
        if (threadIdx.x == 0) {
            if (b == 0) {
                atomicExch(&g_scan_state[0], (2ULL << 32) | (unsigned)total);
                s_prev = 0;
            } else {
                atomicExch(&g_scan_state[b], (1ULL << 32) | (unsigned)total);
                int sum = 0;
                for (int p = b - 1; p >= 0; p--) {
                    unsigned long long w;
                    do { w = atomicAdd(&g_scan_state[p], 0ULL); } while ((w >> 32) == 0);
                    sum += (int)(unsigned)w;
                    if ((w >> 32) == 2) break;
                }
                atomicExch(&g_scan_state[b], (2ULL << 32) | (unsigned)(sum + total));
                s_prev = sum;
            }
        }
        __syncthreads();
        int prev = s_prev;
        if (i < n) g_row_ptr[i + 1] = prev + incl;
        if (i == 0) g_row_ptr[0] = 0;
    } else if (b < nb + fb) {
        // ---- feat -> fp16 (pre-scaled by out_deg^-0.5) ----
        int idx = (b - nb) * 1024 + threadIdx.x;
        if (idx < n * 32) {
            int node = idx >> 5;
            float p = rsqrtf((float)max(g_out_deg[node], 1));
            float4 v0 = feat4[(size_t)idx * 2];
            float4 v1 = feat4[(size_t)idx * 2 + 1];
            __half2 h[4];
            h[0] = __floats2half2_rn(v0.x * p, v0.y * p);
            h[1] = __floats2half2_rn(v0.z * p, v0.w * p);
            h[2] = __floats2half2_rn(v1.x * p, v1.y * p);
            h[3] = __floats2half2_rn(v1.z * p, v1.w * p);
            *(uint4*)&g_feat16[(size_t)idx * 8] = *(uint4*)h;
        }
    } else {
        // ---- W[k][n] -> g_wt16[n][k] fp16 (one 32x32 tile per block) ----
        float* sh = (float*)s;   // 32 x 33
        int bt = b - nb - fb;
        int bx = bt & 7, by = bt >> 3;
        int tx = threadIdx.x & 31, ty = threadIdx.x >> 5;
        sh[ty * 33 + tx] = W[(size_t)(by * 32 + ty) * D + bx * 32 + tx];
        __syncthreads();
        g_wt16[(size_t)(bx * 32 + ty) * D + by * 32 + tx] = __float2half_rn(sh[tx * 33 + ty]);
    }
}

__global__ void k_fill(const int* __restrict__ src, const int* __restrict__ dst, int e) {
    int i = blockIdx.x * blockDim.x + threadIdx.x;
    if (i < e) {
        int d = dst[i];
        int pos = g_row_ptr[d] + atomicAdd(&g_fill[d], 1);
        g_csr_src[pos] = src[i];
    }
}

// ======================= aggregation =======================
// fp16 gather; pairwise fp16 edge-sum, then packed f32x2 accumulate.
// 2-edge software pipeline (prefetch next indices) to hide idx->gather dependency;
// low register count -> full occupancy.
__device__ __forceinline__ unsigned long long pack_f2(float2 f) {
    unsigned long long r;
    asm("mov.b64 %0, {%1, %2};" : "=l"(r) : "f"(f.x), "f"(f.y));
    return r;
}

__device__ __forceinline__ void accpair(unsigned long long* acc, uint4 u0, uint4 u1) {
    __half2* h0 = (__half2*)&u0;
    __half2* h1 = (__half2*)&u1;
#pragma unroll
    for (int i = 0; i < 4; i++) {
        __half2 p = __hadd2(h0[i], h1[i]);
        float2 fp = __half22float2(p);
        asm("add.rn.f32x2 %0, %0, %1;" : "+l"(acc[i]) : "l"(pack_f2(fp)));
    }
}

__device__ __forceinline__ void accone(unsigned long long* acc, uint4 u0) {
    __half2* h0 = (__half2*)&u0;
#pragma unroll
    for (int i = 0; i < 4; i++) {
        float2 fp = __half22float2(h0[i]);
        asm("add.rn.f32x2 %0, %0, %1;" : "+l"(acc[i]) : "l"(pack_f2(fp)));
    }
}

__global__ __launch_bounds__(256) void k_agg(int n) {
    int node = blockIdx.x * 8 + (threadIdx.x >> 5);
    int lane = threadIdx.x & 31;
    if (node >= n) return;
    int beg = g_row_ptr[node];
    int end = g_row_ptr[node + 1];
    const uint4* f = (const uint4*)g_feat16;  // 32 uint4 per row
    unsigned long long acc[4] = {0ULL, 0ULL, 0ULL, 0ULL};  // 8 packed fp32
    int j = beg;
    int i0 = 0, i1 = 0;
    if (j + 2 <= end) { i0 = g_csr_src[j]; i1 = g_csr_src[j + 1]; }
    while (j + 2 <= end) {
        uint4 u0 = f[(size_t)i0 * 32 + lane];
        uint4 u1 = f[(size_t)i1 * 32 + lane];
        j += 2;
        if (j + 2 <= end) { i0 = g_csr_src[j]; i1 = g_csr_src[j + 1]; }
        accpair(acc, u0, u1);
    }
    if (j < end) {
        accone(acc, f[(size_t)g_csr_src[j] * 32 + lane]);
    }
    __half2 h[4];
#pragma unroll
    for (int i = 0; i < 4; i++) {
        float lo, hi;
        asm("mov.b64 {%0, %1}, %2;" : "=f"(lo), "=f"(hi) : "l"(acc[i]));
        h[i] = __floats2half2_rn(lo, hi);
    }
    *(uint4*)&g_agg16[(size_t)node * D + lane * 8] = *(uint4*)h;
}

// ======================= fp16 warp-MMA GEMM (double-buffered) =======================
#define SAB_STRIDE 40

__device__ __forceinline__ void mma_f16(float* c, const uint32_t* a, const uint32_t* b) {
    asm volatile(
        "mma.sync.aligned.m16n8k16.row.col.f32.f16.f16.f32 "
        "{%0,%1,%2,%3}, {%4,%5,%6,%7}, {%8,%9}, {%0,%1,%2,%3};"
        : "+f"(c[0]), "+f"(c[1]), "+f"(c[2]), "+f"(c[3])
        : "r"(a[0]), "r"(a[1]), "r"(a[2]), "r"(a[3]), "r"(b[0]), "r"(b[1]));
}

__global__ __launch_bounds__(256, 2) void k_gemm_mma(const float* __restrict__ bias,
                                                     float* __restrict__ out, int n) {
    __shared__ __half sA[2][128 * SAB_STRIDE];
    __shared__ __half sB[2][128 * SAB_STRIDE];

    const int tid = threadIdx.x;
    const int wid = tid >> 5;
    const int lid = tid & 31;
    const int g   = lid >> 2;
    const int t   = lid & 3;
    const int wm  = wid & 1;
    const int wn  = wid >> 1;

    const int row0 = blockIdx.y * 128;
    const int n0   = blockIdx.x * 128;
    const int arows = min(128, n - row0);

    const int st_r  = tid >> 2;
    const int st_c8 = (tid & 3) * 8;

    float acc[4][4][4];
#pragma unroll
    for (int mf = 0; mf < 4; mf++)
#pragma unroll
        for (int nf = 0; nf < 4; nf++)
#pragma unroll
            for (int r = 0; r < 4; r++) acc[mf][nf][r] = 0.f;

    uint4 ua[2], ub[2];
#pragma unroll
    for (int i = 0; i < 2; i++) {
        int r = st_r + i * 64;
        ua[i] = make_uint4(0, 0, 0, 0);
        if (r < arows) ua[i] = *(const uint4*)&g_agg16[(size_t)(row0 + r) * D + st_c8];
        ub[i] = *(const uint4*)&g_wt16[(size_t)(n0 + r) * D + st_c8];
    }
#pragma unroll
    for (int i = 0; i < 2; i++) {
        int r = st_r + i * 64;
        *(uint4*)&sA[0][r * SAB_STRIDE + st_c8] = ua[i];
        *(uint4*)&sB[0][r * SAB_STRIDE + st_c8] = ub[i];
    }
    __syncthreads();

    for (int kc = 0; kc < 8; kc++) {
        const int cur = kc & 1;
        if (kc < 7) {
            const int kb = (kc + 1) * 32;
#pragma unroll
            for (int i = 0; i < 2; i++) {
                int r = st_r + i * 64;
                ua[i] = make_uint4(0, 0, 0, 0);
                if (r < arows) ua[i] = *(const uint4*)&g_agg16[(size_t)(row0 + r) * D + kb + st_c8];
                ub[i] = *(const uint4*)&g_wt16[(size_t)(n0 + r) * D + kb + st_c8];
            }
        }
#pragma unroll
        for (int ks = 0; ks < 2; ks++) {
            const int k0 = ks * 16;
            uint32_t af[4][4], bf[4][2];
#pragma unroll
            for (int mf = 0; mf < 4; mf++) {
                int mrow = wm * 64 + mf * 16 + g;
                const __half* base = &sA[cur][mrow * SAB_STRIDE + k0 + 2 * t];
                af[mf][0] = *(const uint32_t*)(base);
                af[mf][1] = *(const uint32_t*)(base + 8 * SAB_STRIDE);
                af[mf][2] = *(const uint32_t*)(base + 8);
                af[mf][3] = *(const uint32_t*)(base + 8 * SAB_STRIDE + 8);
            }
#pragma unroll
            for (int nf = 0; nf < 4; nf++) {
                int ncol = wn * 32 + nf * 8 + g;
                const __half* base = &sB[cur][ncol * SAB_STRIDE + k0 + 2 * t];
                bf[nf][0] = *(const uint32_t*)(base);
                bf[nf][1] = *(const uint32_t*)(base + 8);
            }
#pragma unroll
            for (int mf = 0; mf < 4; mf++)
#pragma unroll
                for (int nf = 0; nf < 4; nf++)
                    mma_f16(acc[mf][nf], af[mf], bf[nf]);
        }
        if (kc < 7) {
            const int nxt = cur ^ 1;
#pragma unroll
            for (int i = 0; i < 2; i++) {
                int r = st_r + i * 64;
                *(uint4*)&sA[nxt][r * SAB_STRIDE + st_c8] = ua[i];
                *(uint4*)&sB[nxt][r * SAB_STRIDE + st_c8] = ub[i];
            }
            __syncthreads();
        }
    }

#pragma unroll
    for (int mf = 0; mf < 4; mf++) {
        int r0 = row0 + wm * 64 + mf * 16 + g;
        int r1 = r0 + 8;
        float post0 = 0.f, post1 = 0.f;
        if (r0 < n) post0 = rsqrtf(fmaxf((float)g_in_deg[r0], 1.f));
        if (r1 < n) post1 = rsqrtf(fmaxf((float)g_in_deg[r1], 1.f));
#pragma unroll
        for (int nf = 0; nf < 4; nf++) {
            int c = n0 + wn * 32 + nf * 8 + t * 2;
            float2 b2 = *(const float2*)&bias[c];
            if (r0 < n) {
                float2 v;
                v.x = acc[mf][nf][0] * post0 + b2.x;
                v.y = acc[mf][nf][1] * post0 + b2.y;
                *(float2*)&out[(size_t)r0 * D + c] = v;
            }
            if (r1 < n) {
                float2 v;
                v.x = acc[mf][nf][2] * post1 + b2.x;
                v.y = acc[mf][nf][3] * post1 + b2.y;
                *(float2*)&out[(size_t)r1 * D + c] = v;
            }
        }
    }
}

// zero scratch counters for the NEXT invocation (globals start zeroed at load)
__global__ void k_zero_tail(int n) {
    int i = blockIdx.x * blockDim.x + threadIdx.x;
    if (i < n) { g_out_deg[i] = 0; g_in_deg[i] = 0; g_fill[i] = 0; }
    if (i < 128) g_scan_state[i] = 0ULL;
}

// ======================= launch =======================
extern "C" void kernel_launch(void* const* d_in, const int* in_sizes, int n_in,
                              void* d_out, int out_size) {
    const float* feat   = (const float*)d_in[0];
    const int*   src    = (const int*)d_in[1];
    const int*   dst    = (const int*)d_in[2];
    const float* weight = (const float*)d_in[3];
    const float* bias   = (const float*)d_in[4];
    float*       out    = (float*)d_out;

    int n = in_sizes[0] / D;   // 100000
    int e = in_sizes[1];       // 1600000

    int nb = (n + 1023) / 1024;           // 98 scan blocks
    int fb = (n * 32 + 1023) / 1024;      // 3125 feat-convert blocks
    int wb = 64;                          // W transpose blocks

    k_deg<<<(e + 255) / 256, 256>>>(src, dst, e);                        // 0
    k_mid<<<nb + fb + wb, 1024>>>((const float4*)feat, weight, n, nb, fb); // 1
    k_fill<<<(e + 255) / 256, 256>>>(src, dst, e);                       // 2
    k_agg<<<(n + 7) / 8, 256>>>(n);                                      // 3  <- profiled
    dim3 gg(2, (n + 127) / 128);
    k_gemm_mma<<<gg, 256>>>(bias, out, n);                               // 4
    k_zero_tail<<<(n + 255) / 256, 256>>>(n);                            // 5
}